// round 7
// baseline (speedup 1.0000x reference)
#include <cuda_runtime.h>
#include <cuda_bf16.h>
#include <mma.h>

using namespace nvcuda;

#define B_SZ 256
#define IN_DIM 1024
#define NK 100
#define DK 50
#define NOUT 5000
#define NPAD 5056              // padded N: 79 tiles of 64
#define OUT_DIM (IN_DIM + NK)  // 1124

#define QROW 52                // bytes per (k,i) row: 50 + 2 pad
#define QW 13                  // u32 words per row

// -------------------- device scratch (no cudaMalloc allowed) ---------------
__device__ __nv_bfloat16  g_xb[B_SZ * IN_DIM];            // x in bf16
__device__ unsigned char  g_actq8[NK * B_SZ * QROW];      // u8 quantized act

// ---------------------------------------------------------------------------
// prep: x fp32 -> bf16 ; out init ; g_actq8 pad bytes = 128
// ---------------------------------------------------------------------------
#define XB_UNITS (B_SZ * IN_DIM / 4)     // 65536
#define OI_UNITS (B_SZ * OUT_DIM / 4)    // 71936
#define PAD_UNITS (NK * B_SZ)            // 25600

__global__ void prep_kernel(const float* __restrict__ x,
                            float* __restrict__ out) {
    int t = blockIdx.x * blockDim.x + threadIdx.x;
    if (t < XB_UNITS) {
        float4 v = ((const float4*)x)[t];
        __nv_bfloat162* dst = (__nv_bfloat162*)&g_xb[t * 4];
        dst[0] = __float22bfloat162_rn(make_float2(v.x, v.y));
        dst[1] = __float22bfloat162_rn(make_float2(v.z, v.w));
        return;
    }
    t -= XB_UNITS;
    if (t < OI_UNITS) {
        int row = t / (OUT_DIM / 4);
        int c4  = t % (OUT_DIM / 4);
        float4 v = make_float4(0.f, 0.f, 0.f, 0.f);
        if (c4 < IN_DIM / 4) v = ((const float4*)x)[row * (IN_DIM / 4) + c4];
        ((float4*)out)[row * (OUT_DIM / 4) + c4] = v;
        return;
    }
    t -= OI_UNITS;
    if (t < PAD_UNITS) {
        // pad bytes d=50,51 <- 128 so SAD over pads is 0
        *(unsigned short*)&g_actq8[t * QROW + DK] = 0x8080;
    }
}

// ---------------------------------------------------------------------------
// GEMM + fused quantization.
// act = bf16(x) @ bf16(w), fp32 accum; epilogue quantizes round(32*act)+128
// to u8 straight into g_actq8 (no fp32 act in gmem at all).
// Block tile 128x64, GBK=64, 8 warps (4M x 2N), warp tile 32x32.
// 2-stage smem double buffer + register prefetch, one barrier per iter.
// ---------------------------------------------------------------------------
#define GBM 128
#define GBN 64
#define GBK 64
#define ALD 72     // bf16 row stride for A tile
#define BLD 72     // bf16 row stride for B tile
#define ELD 68     // fp32 row stride for epilogue tile

#define A_STAGE_BYTES (GBM * ALD * 2)          // 18432
#define B_STAGE_BYTES (GBK * BLD * 2)          // 9216
#define SMEM_BYTES (2 * (A_STAGE_BYTES + B_STAGE_BYTES))   // 55296 (> 128*68*4)

__global__ __launch_bounds__(256) void gemm_kernel(const float* __restrict__ w) {
    __shared__ __align__(16) unsigned char smem_raw[SMEM_BYTES];
    __nv_bfloat16* As = (__nv_bfloat16*)smem_raw;                       // [2][128][72]
    __nv_bfloat16* Bs = (__nv_bfloat16*)(smem_raw + 2 * A_STAGE_BYTES); // [2][64][72]
    float*         Es = (float*)smem_raw;                               // [128][68]

    int tid = threadIdx.x;
    int n0 = blockIdx.x * GBN;
    int m0 = blockIdx.y * GBM;
    int warp   = tid / 32;
    int wm = (warp / 2) * 32;     // 4 warps along M
    int wn = (warp % 2) * 32;     // 2 warps along N

    // per-thread load coords
    int a_row = tid / 8;                 // 0..31 (x4 via p)
    int a_c8  = (tid % 8) * 8;
    int b_row = tid / 16;                // 0..15 (x4 via p)
    int b_c4  = (tid % 16) * 4;

    uint4  a_reg[4];
    float4 b_reg[4];

    auto load_regs = [&](int kk) {
        #pragma unroll
        for (int p = 0; p < 4; p++) {
            int row = a_row + p * 32;
            a_reg[p] = *(const uint4*)&g_xb[(m0 + row) * IN_DIM + kk + a_c8];
        }
        #pragma unroll
        for (int p = 0; p < 4; p++) {
            int row = b_row + p * 16;
            int n = n0 + b_c4;
            b_reg[p] = (n < NOUT)
                ? *(const float4*)&w[(long long)(kk + row) * NOUT + n]
                : make_float4(0.f, 0.f, 0.f, 0.f);
        }
    };

    auto sts = [&](int st) {
        __nv_bfloat16* Ab = As + st * GBM * ALD;
        __nv_bfloat16* Bb = Bs + st * GBK * BLD;
        #pragma unroll
        for (int p = 0; p < 4; p++)
            *(uint4*)&Ab[(a_row + p * 32) * ALD + a_c8] = a_reg[p];
        #pragma unroll
        for (int p = 0; p < 4; p++) {
            __nv_bfloat162* dst = (__nv_bfloat162*)&Bb[(b_row + p * 16) * BLD + b_c4];
            dst[0] = __float22bfloat162_rn(make_float2(b_reg[p].x, b_reg[p].y));
            dst[1] = __float22bfloat162_rn(make_float2(b_reg[p].z, b_reg[p].w));
        }
    };

    wmma::fragment<wmma::matrix_a, 16, 16, 16, __nv_bfloat16, wmma::row_major> af[2];
    wmma::fragment<wmma::matrix_b, 16, 16, 16, __nv_bfloat16, wmma::row_major> bf[2];
    wmma::fragment<wmma::accumulator, 16, 16, 16, float> cf[2][2];
    #pragma unroll
    for (int i = 0; i < 2; i++)
        #pragma unroll
        for (int j = 0; j < 2; j++) wmma::fill_fragment(cf[i][j], 0.0f);

    load_regs(0);
    sts(0);

    const int KT = IN_DIM / GBK;   // 16
    for (int kt = 0; kt < KT; kt++) {
        __syncthreads();
        if (kt + 1 < KT) load_regs((kt + 1) * GBK);

        const __nv_bfloat16* Ab = As + (kt & 1) * GBM * ALD;
        const __nv_bfloat16* Bb = Bs + (kt & 1) * GBK * BLD;
        #pragma unroll
        for (int ks = 0; ks < GBK / 16; ks++) {
            wmma::load_matrix_sync(af[0], Ab + wm * ALD + ks * 16, ALD);
            wmma::load_matrix_sync(af[1], Ab + (wm + 16) * ALD + ks * 16, ALD);
            wmma::load_matrix_sync(bf[0], Bb + ks * 16 * BLD + wn, BLD);
            wmma::load_matrix_sync(bf[1], Bb + ks * 16 * BLD + wn + 16, BLD);
            #pragma unroll
            for (int i = 0; i < 2; i++)
                #pragma unroll
                for (int j = 0; j < 2; j++)
                    wmma::mma_sync(cf[i][j], af[i], bf[j], cf[i][j]);
        }

        if (kt + 1 < KT) sts((kt + 1) & 1);
    }

    // ---- fused quantization epilogue ----
    __syncthreads();   // done reading As/Bs; smem becomes Es
    #pragma unroll
    for (int i = 0; i < 2; i++)
        #pragma unroll
        for (int j = 0; j < 2; j++)
            wmma::store_matrix_sync(&Es[(wm + i * 16) * ELD + wn + j * 16],
                                    cf[i][j], ELD, wmma::mem_row_major);
    __syncthreads();

    #pragma unroll
    for (int p = 0; p < (GBM * GBN) / 256; p++) {   // 32 elements/thread
        int idx = tid + p * 256;
        int row = idx / GBN;
        int col = idx % GBN;
        int n = n0 + col;
        if (n < NOUT) {
            float v = Es[row * ELD + col];
            int qi = __float2int_rn(v * 32.0f);
            qi = max(-127, min(127, qi)) + 128;
            int k = n / DK;
            int d = n % DK;
            g_actq8[(k * B_SZ + m0 + row) * QROW + d] = (unsigned char)qi;
        }
    }
}

// ---------------------------------------------------------------------------
// features[i,k] = sum_j exp(-sum_d |act[i,k,d]-act[j,k,d]|)   via u8 SAD
// grid = (NK, 8): block = kernel k, 32-row j-chunk, 256 threads = 256 i.
// ---------------------------------------------------------------------------
#define JC 32

__device__ __forceinline__ unsigned vad4(unsigned a, unsigned b, unsigned c) {
    unsigned d;
    asm("vabsdiff4.u32.u32.u32.add %0, %1, %2, %3;"
        : "=r"(d) : "r"(a), "r"(b), "r"(c));
    return d;
}

__global__ __launch_bounds__(256) void feature_kernel(float* __restrict__ out) {
    __shared__ unsigned Aj[JC][QW + 1];

    int k   = blockIdx.x;
    int j0  = blockIdx.y * JC;
    int tid = threadIdx.x;                 // row i
    const unsigned* actk = (const unsigned*)&g_actq8[(long long)k * B_SZ * QROW];

    for (int p = tid; p < JC * QW; p += 256)
        Aj[p / QW][p % QW] = actk[(j0 + p / QW) * QW + p % QW];

    unsigned ai[QW];
    #pragma unroll
    for (int c = 0; c < QW; c++)
        ai[c] = actk[tid * QW + c];

    __syncthreads();

    float s = 0.0f;
    #pragma unroll 4
    for (int j = 0; j < JC; j++) {
        unsigned la = 0, lb = 0;
        #pragma unroll
        for (int c = 0; c < QW - 1; c += 2) {
            la = vad4(ai[c],     Aj[j][c],     la);
            lb = vad4(ai[c + 1], Aj[j][c + 1], lb);
        }
        la = vad4(ai[QW - 1], Aj[j][QW - 1], la);
        s += __expf((float)(la + lb) * (-1.0f / 32.0f));
    }

    atomicAdd(&out[tid * OUT_DIM + IN_DIM + k], s);
}

// ---------------------------------------------------------------------------
extern "C" void kernel_launch(void* const* d_in, const int* in_sizes, int n_in,
                              void* d_out, int out_size) {
    const float* x = (const float*)d_in[0];
    const float* w = (const float*)d_in[1];
    float* out = (float*)d_out;

    int prep_threads = XB_UNITS + OI_UNITS + PAD_UNITS;
    prep_kernel<<<(prep_threads + 255) / 256, 256>>>(x, out);

    dim3 ggrid(NPAD / GBN, B_SZ / GBM);   // (79, 2) = 158 CTAs
    gemm_kernel<<<ggrid, 256>>>(w);

    dim3 fgrid(NK, B_SZ / JC);            // (100, 8) = 800 CTAs
    feature_kernel<<<fgrid, 256>>>(out);
}